// round 15
// baseline (speedup 1.0000x reference)
#include <cuda_runtime.h>
#include <cuda_fp16.h>
#include <cstdint>

#define NROWS (256 * 32 * 32)   // 262144
#define D 64
#define K 1024
#define KC 128                  // codes per smem chunk
#define GAP_RESCUE 4.0e-2f      // ~13 sigma of fp16 coarse noise (+ key truncation)
#define CLUSTER    3.0e-2f      // top-4 key spread below this -> warp full scan
#define SMEM_SZ (KC * 144 + KC * 4)   // fp16 codebook chunk (144B/code) + sq fp32

__device__ float  g_embT[K * D];   // code-major codebook [k][d] fp32 (exact paths)
__device__ float  g_sqe[K];        // ||e_k||^2 exact fp32
__device__ float  g_sq8[K];        // sqe_k + 8 (fp32, keeps coarse score positive)
__device__ uint4  g_E16[K * 8];    // half2-packed codebook, 8 x uint4 (128B) per code
__device__ double g_acc;

// H1 bit-exact emulation of the reference arithmetic (identical decision math to the
// passing R7/R9/R12/R14 path); x read from global (cold path).
__device__ __noinline__ int h1_emulate_g(const float* __restrict__ xg, int lo, int hi) {
    float l0 = 0.f, l1 = 0.f, l2 = 0.f, l3 = 0.f;
    #pragma unroll 4
    for (int d = 0; d < 64; d += 4) {
        l0 = fmaf(xg[d],     xg[d],     l0);
        l1 = fmaf(xg[d + 1], xg[d + 1], l1);
        l2 = fmaf(xg[d + 2], xg[d + 2], l2);
        l3 = fmaf(xg[d + 3], xg[d + 3], l3);
    }
    float A = (l0 + l1) + (l2 + l3);
    float Bl = 0.f, Bh = 0.f, dl = 0.f, dh = 0.f;
    #pragma unroll 8
    for (int d = 0; d < 64; d++) {
        float el = g_embT[lo * D + d], eh = g_embT[hi * D + d];
        Bl = fmaf(el, el, Bl);
        Bh = fmaf(eh, eh, Bh);
        dl = fmaf(xg[d], el, dl);
        dh = fmaf(xg[d], eh, dh);
    }
    float distlo = (A + Bl) - 2.0f * dl;
    float disthi = (A + Bh) - 2.0f * dh;
    return (disthi < distlo) ? hi : lo;   // strict '<': ties -> lower index
}

// ---------------- init ----------------
__global__ void vq_init_kernel(const float* __restrict__ emb) {
    int i = blockIdx.x * blockDim.x + threadIdx.x;   // 65536 threads
    if (i == 0) g_acc = 0.0;
    if (i < K * D) {
        int d = i >> 10;            // emb is [d][k]
        int k = i & (K - 1);
        g_embT[k * D + d] = emb[i];
    }
    if (i < K) {
        float s = 0.f;
        #pragma unroll 8
        for (int d = 0; d < D; d++) {
            float v = emb[d * K + i];
            s = fmaf(v, v, s);
        }
        g_sqe[i] = s;
        g_sq8[i] = s + 8.0f;
        // half2-packed code row: word j = half2(e_{2j}, e_{2j+1})
        unsigned w[32];
        #pragma unroll 8
        for (int j = 0; j < 32; j++) {
            __half2 h = __floats2half2_rn(emb[(2 * j) * K + i], emb[(2 * j + 1) * K + i]);
            w[j] = *reinterpret_cast<unsigned*>(&h);
        }
        #pragma unroll
        for (int q = 0; q < 8; q++)
            g_E16[i * 8 + q] = make_uint4(w[4 * q], w[4 * q + 1], w[4 * q + 2], w[4 * q + 3]);
    }
}

// ---------------- mega: fp16 HFMA2 coarse + exact rescue + output + loss ----------------
__global__ void __launch_bounds__(256) vq_mega(const float* __restrict__ x,
                                               float* __restrict__ out) {
    extern __shared__ char smem[];
    uint4* sE = (uint4*)smem;                          // KC codes x 9 uint4 (144B stride)
    float* sQ = (float*)(smem + KC * 144);             // KC floats (sqe + 8)
    __shared__ double sred[8];
    int tid = threadIdx.x, lane = tid & 31;
    int row = blockIdx.x * 256 + tid;

    // x row as 32 half2 of -2x (coarse only; exact paths re-read x from global)
    __half2 xh[32];
    {
        const float2* xp = (const float2*)(x + (size_t)row * D);
        #pragma unroll
        for (int j = 0; j < 32; j++) {
            float2 v = xp[j];
            xh[j] = __floats2half2_rn(-2.0f * v.x, -2.0f * v.y);
        }
    }

    unsigned k0 = 0xFFFFFFFFu, k1 = 0xFFFFFFFFu, k2 = 0xFFFFFFFFu, k3 = 0xFFFFFFFFu;

    for (int c0 = 0; c0 < K; c0 += KC) {
        __syncthreads();
        #pragma unroll
        for (int i = tid; i < KC * 8; i += 256) {
            int code = i >> 3, q = i & 7;
            sE[code * 9 + q] = g_E16[(c0 + code) * 8 + q];
        }
        if (tid < KC) sQ[tid] = g_sq8[c0 + tid];
        __syncthreads();

        const char* ecur = (const char*)sE;
        const char* qcur = (const char*)sQ;
        unsigned code = (unsigned)c0;
        #pragma unroll 4
        for (int kc = 0; kc < KC; kc++) {
            const uint4* ep = (const uint4*)ecur;
            __half2 a0 = __float2half2_rn(0.f), a1 = __float2half2_rn(0.f);
            #pragma unroll
            for (int i = 0; i < 8; i++) {
                uint4 e = ep[i];
                a0 = __hfma2(xh[4 * i + 0], *reinterpret_cast<const __half2*>(&e.x), a0);
                a1 = __hfma2(xh[4 * i + 1], *reinterpret_cast<const __half2*>(&e.y), a1);
                a0 = __hfma2(xh[4 * i + 2], *reinterpret_cast<const __half2*>(&e.z), a0);
                a1 = __hfma2(xh[4 * i + 3], *reinterpret_cast<const __half2*>(&e.w), a1);
            }
            __half2 am = __hadd2(a0, a1);
            float2 f = __half22float2(am);
            float val = (f.x + f.y) + *(const float*)qcur;   // ~[6.5,9.6] > 0
            unsigned key = (__float_as_uint(val) & 0xFFFFFC00u) | code;
            unsigned t = key, m;
            m = min(k0, t); t = max(k0, t); k0 = m;
            m = min(k1, t); t = max(k1, t); k1 = m;
            m = min(k2, t); t = max(k2, t); k2 = m;
            k3 = min(k3, t);
            ecur += 144;
            qcur += 4;
            code++;
        }
    }

    // ---- rescue ----
    float s0 = __uint_as_float(k0 & 0xFFFFFC00u);
    float s1 = __uint_as_float(k1 & 0xFFFFFC00u);
    float s3 = __uint_as_float(k3 & 0xFFFFFC00u);
    int widx = (int)(k0 & 1023u);
    bool rescue = (s1 - s0 < GAP_RESCUE);
    bool full   = rescue && (s3 - s0 < CLUSTER);

    // warp-cooperative exact full scans for clustered rows (rare)
    unsigned fmask = __ballot_sync(0xffffffffu, full);
    while (fmask) {
        int src = __ffs(fmask) - 1;
        fmask &= fmask - 1;
        int r = __shfl_sync(0xffffffffu, row, src);
        const float* xg = x + (size_t)r * D;
        float b0 = 3e38f, b1 = 3e38f;
        int i0 = 0, i1 = 0;
        for (int k = lane; k < K; k += 32) {
            const float* e = &g_embT[k * D];
            float dot = 0.f;
            #pragma unroll 8
            for (int d = 0; d < D; d++) dot = fmaf(xg[d], e[d], dot);
            float val = fmaf(dot, -2.f, g_sqe[k]);
            if (val < b0)      { b1 = b0; i1 = i0; b0 = val; i0 = k; }
            else if (val < b1) { b1 = val; i1 = k; }
        }
        #pragma unroll
        for (int off = 16; off; off >>= 1) {
            float ob0 = __shfl_xor_sync(0xffffffffu, b0, off);
            float ob1 = __shfl_xor_sync(0xffffffffu, b1, off);
            int   oi0 = __shfl_xor_sync(0xffffffffu, i0, off);
            int   oi1 = __shfl_xor_sync(0xffffffffu, i1, off);
            bool owin = (ob0 < b0) || (ob0 == b0 && oi0 < i0);
            if (owin) {
                float tf = b0; b0 = ob0; ob0 = tf;
                int   ti = i0; i0 = oi0; oi0 = ti;
                tf = b1; b1 = ob1; ob1 = tf;
                ti = i1; i1 = oi1; oi1 = ti;
            }
            if ((ob0 < b1) || (ob0 == b1 && oi0 < i1)) { b1 = ob0; i1 = oi0; }
        }
        if (lane == src)
            widx = (b1 - b0 < 1e-3f) ? h1_emulate_g(xg, min(i0, i1), max(i0, i1)) : i0;
    }

    if (rescue && !full) {
        // exact fp32 rescore of key top-4, x from global (L1-hot across candidates)
        const float* xg = x + (size_t)row * D;
        int ids[4] = { (int)(k0 & 1023u), (int)(k1 & 1023u),
                       (int)(k2 & 1023u), (int)(k3 & 1023u) };
        #pragma unroll
        for (int a = 1; a < 4; a++) {
            int v = ids[a], b = a;
            while (b > 0 && ids[b - 1] > v) { ids[b] = ids[b - 1]; b--; }
            ids[b] = v;
        }
        float b0 = 3e38f, b1 = 3e38f;
        int i0 = 0, i1 = 0;
        #pragma unroll
        for (int j = 0; j < 4; j++) {
            const float* e = &g_embT[ids[j] * D];
            float dot = 0.f;
            #pragma unroll 8
            for (int d = 0; d < D; d++) dot = fmaf(xg[d], e[d], dot);
            float val = fmaf(dot, -2.f, g_sqe[ids[j]]);
            if (val < b0)      { b1 = b0; i1 = i0; b0 = val; i0 = ids[j]; }
            else if (val < b1) { b1 = val; i1 = ids[j]; }
        }
        widx = (b1 - b0 < 1e-3f) ? h1_emulate_g(xg, min(i0, i1), max(i0, i1)) : i0;
    }

    // ---- output + loss: exact x from global (byte-identical to proven R12 phase-B) ----
    const float4* qv4 = (const float4*)&g_embT[widx * D];
    const float4* xp4 = (const float4*)(x + (size_t)row * D);
    float4* o4 = (float4*)(out + (size_t)row * D);
    double local = 0.0;
    #pragma unroll
    for (int i = 0; i < 16; i++) {
        float4 q = qv4[i];
        float4 xv = xp4[i];
        float d0 = q.x - xv.x, d1 = q.y - xv.y, d2 = q.z - xv.z, d3 = q.w - xv.w;
        float4 o;
        o.x = xv.x + d0; o.y = xv.y + d1; o.z = xv.z + d2; o.w = xv.w + d3;
        o4[i] = o;
        local += (double)d0 * d0 + (double)d1 * d1 + (double)d2 * d2 + (double)d3 * d3;
    }
    #pragma unroll
    for (int off = 16; off > 0; off >>= 1)
        local += __shfl_down_sync(0xffffffffu, local, off);
    int w = tid >> 5;
    if (lane == 0) sred[w] = local;
    __syncthreads();
    if (tid == 0) {
        double s = 0.0;
        #pragma unroll
        for (int k = 0; k < 8; k++) s += sred[k];
        atomicAdd(&g_acc, s);
    }
}

__global__ void vq_finalize_kernel(float* __restrict__ loss_out) {
    double m = g_acc / (double)((long)NROWS * D);
    float lf = (float)m;
    *loss_out = 0.25f * lf + lf;   // BETA*commitment + codebook (equal values)
}

extern "C" void kernel_launch(void* const* d_in, const int* in_sizes, int n_in,
                              void* d_out, int out_size) {
    const float* x   = (const float*)d_in[0];   // [256,32,32,64] fp32
    const float* emb = (const float*)d_in[1];   // [64,1024] fp32
    float* out = (float*)d_out;

    cudaFuncSetAttribute(vq_mega, cudaFuncAttributeMaxDynamicSharedMemorySize, SMEM_SZ);

    vq_init_kernel<<<256, 256>>>(emb);
    vq_mega<<<NROWS / 256, 256, SMEM_SZ>>>(x, out);
    vq_finalize_kernel<<<1, 1>>>(out + (out_size - 1));
}

// round 16
// speedup vs baseline: 4.1107x; 4.1107x over previous
#include <cuda_runtime.h>
#include <cuda_bf16.h>
#include <cstdint>

#define NROWS (256 * 32 * 32)   // 262144
#define D 64
#define K 1024
#define TILE_M 128              // rows per coarse CTA (4 warps x 32 rows)
#define CHUNKC 256              // codes per smem chunk

// smem: A 128x144B | B 256x144B | sq8 256 f32
#define SMB_OFF   (TILE_M * 144)
#define SMQ_OFF   (SMB_OFF + CHUNKC * 144)
#define SMEM_SZ   (SMQ_OFF + CHUNKC * 4)

#define GAP_ACCEPT 1.0e-2f      // proven R9 accept threshold
#define CLUSTER    6.0e-3f      // top-4 key spread below this -> warp full scan

__device__ float    g_embT[K * D];     // code-major codebook [k][d] fp32 (exact paths)
__device__ float    g_sqe[K];          // ||e_k||^2 exact fp32
__device__ float    g_sq8[K];          // sqe + 8 (coarse bias, keeps scores positive)
__device__ unsigned g_Bpk[K * 32];     // bf16x2 codebook in mma-B-fragment order (R9 layout)
__device__ uint4    g_c12[NROWS * 4];  // per row: 4 quad-lanes x {3 keys + sentinel}
__device__ double   g_acc;

// ---------------- helpers (R9 verbatim where proven) ----------------
__device__ __forceinline__ unsigned bfbits(float f) {
    return (unsigned)__bfloat16_as_ushort(__float2bfloat16(f));
}
__device__ __forceinline__ uint32_t smem_u32(const void* p) {
    uint32_t a;
    asm("{ .reg .u64 t; cvta.to.shared.u64 t, %1; cvt.u32.u64 %0, t; }" : "=r"(a) : "l"(p));
    return a;
}
__device__ __forceinline__ void ldmat4(unsigned r[4], uint32_t saddr) {
    asm volatile("ldmatrix.sync.aligned.m8n8.x4.shared.b16 {%0,%1,%2,%3}, [%4];"
        : "=r"(r[0]), "=r"(r[1]), "=r"(r[2]), "=r"(r[3]) : "r"(saddr));
}
__device__ __forceinline__ void mma_bf16(float& d0, float& d1, float& d2, float& d3,
                                         const unsigned a[4], unsigned b0, unsigned b1) {
    asm volatile("mma.sync.aligned.m16n8k16.row.col.f32.bf16.bf16.f32 "
        "{%0,%1,%2,%3}, {%4,%5,%6,%7}, {%8,%9}, {%0,%1,%2,%3};"
        : "+f"(d0), "+f"(d1), "+f"(d2), "+f"(d3)
        : "r"(a[0]), "r"(a[1]), "r"(a[2]), "r"(a[3]), "r"(b0), "r"(b1));
}
// branchless 3-deep / 4-deep key insertion (unsigned order == score order; code in low 10 bits)
#define INS3(K0, K1, K2, key) do { unsigned _t = (key), _m; \
    _m = min(K0, _t); _t = max(K0, _t); K0 = _m; \
    _m = min(K1, _t); _t = max(K1, _t); K1 = _m; \
    K2 = min(K2, _t); } while (0)
#define INS4(K0, K1, K2, K3, key) do { unsigned _t = (key), _m; \
    _m = min(K0, _t); _t = max(K0, _t); K0 = _m; \
    _m = min(K1, _t); _t = max(K1, _t); K1 = _m; \
    _m = min(K2, _t); _t = max(K2, _t); K2 = _m; \
    K3 = min(K3, _t); } while (0)

// H1 bit-exact emulation of the reference arithmetic (identical decision math to the
// passing R7/R9/R12/R14 path); x read from global (cold path).
__device__ __noinline__ int h1_emulate_g(const float* __restrict__ xg, int lo, int hi) {
    float l0 = 0.f, l1 = 0.f, l2 = 0.f, l3 = 0.f;
    #pragma unroll 4
    for (int d = 0; d < 64; d += 4) {
        l0 = fmaf(xg[d],     xg[d],     l0);
        l1 = fmaf(xg[d + 1], xg[d + 1], l1);
        l2 = fmaf(xg[d + 2], xg[d + 2], l2);
        l3 = fmaf(xg[d + 3], xg[d + 3], l3);
    }
    float A = (l0 + l1) + (l2 + l3);
    float Bl = 0.f, Bh = 0.f, dl = 0.f, dh = 0.f;
    #pragma unroll 8
    for (int d = 0; d < 64; d++) {
        float el = g_embT[lo * D + d], eh = g_embT[hi * D + d];
        Bl = fmaf(el, el, Bl);
        Bh = fmaf(eh, eh, Bh);
        dl = fmaf(xg[d], el, dl);
        dh = fmaf(xg[d], eh, dh);
    }
    float distlo = (A + Bl) - 2.0f * dl;
    float disthi = (A + Bh) - 2.0f * dh;
    return (disthi < distlo) ? hi : lo;   // strict '<': ties -> lower index
}

// ---------------- init: transpose, sqe, fragment-packed bf16 codebook ----------------
__global__ void vq_init_kernel(const float* __restrict__ emb) {
    int i = blockIdx.x * blockDim.x + threadIdx.x;   // 65536 threads
    if (i == 0) g_acc = 0.0;
    if (i < K * D) {
        int d = i >> 10;            // emb is [d][k]
        int k = i & (K - 1);
        g_embT[k * D + d] = emb[i];
    }
    if (i < K) {
        float s = 0.f;
        #pragma unroll 8
        for (int d = 0; d < D; d++) {
            float v = emb[d * K + i];
            s = fmaf(v, v, s);
        }
        g_sqe[i] = s;
        g_sq8[i] = s + 8.0f;
    }
    if (i < K * 32) {   // R9-proven B-fragment packing
        int c = i >> 5, p = i & 31;
        float e0 = emb[(2 * p) * K + c], e1 = emb[(2 * p + 1) * K + c];
        unsigned v = bfbits(e0) | (bfbits(e1) << 16);
        int s = p >> 3, rem = p & 7, b = rem >> 2, q = rem & 3;
        g_Bpk[c * 32 + q * 8 + s * 2 + b] = v;
    }
}

// ---------------- coarse: bf16 mma, independent accum chains, branchless top-3 keys ----
__global__ void __launch_bounds__(128) vq_coarse(const float* __restrict__ x) {
    extern __shared__ char smem[];
    uint4* sB  = (uint4*)(smem + SMB_OFF);   // code stride 9 uint4 (144B)
    float* sSq = (float*)(smem + SMQ_OFF);

    int tid = threadIdx.x, w = tid >> 5, l = tid & 31, q = l & 3;
    int rowbase = blockIdx.x * TILE_M;

    // A = bf16(-2x), 128 rows x 64 dims, 144B row stride (R9 verbatim)
    for (int it = tid; it < TILE_M * 32; it += 128) {
        int r = it >> 5, p = it & 31;
        float2 xv = ((const float2*)x)[(size_t)(rowbase + r) * 32 + p];
        unsigned v = bfbits(-2.f * xv.x) | (bfbits(-2.f * xv.y) << 16);
        *(unsigned*)((char*)smem + r * 144 + p * 4) = v;
    }
    __syncthreads();

    // A fragments (R9 verbatim): warp w owns rows [w*32, w*32+32)
    unsigned afr[2][4][4];
    {
        int rr = (l & 15), cc = (l >> 4) * 8;
        #pragma unroll
        for (int t = 0; t < 2; t++) {
            int R = w * 32 + t * 16 + rr;
            #pragma unroll
            for (int s = 0; s < 4; s++) {
                uint32_t ad = smem_u32((char*)smem + R * 144 + (cc + s * 16) * 2);
                ldmat4(afr[t][s], ad);
            }
        }
    }

    // per-thread: 4 m-slots x top-3 keys
    unsigned Kk[4][3];
    #pragma unroll
    for (int m = 0; m < 4; m++) { Kk[m][0] = Kk[m][1] = Kk[m][2] = 0xFFFFFFFFu; }

    for (int ch = 0; ch < K / CHUNKC; ch++) {
        __syncthreads();
        const uint4* gB = ((const uint4*)g_Bpk) + ch * CHUNKC * 8;
        for (int j = tid; j < CHUNKC * 8; j += 128)
            sB[(j >> 3) * 9 + (j & 7)] = gB[j];
        for (int j = tid; j < CHUNKC; j += 128)
            sSq[j] = g_sq8[ch * CHUNKC + j];
        __syncthreads();

        int c0 = ch * CHUNKC;
        #pragma unroll 2
        for (int nt = 0; nt < CHUNKC / 8; nt++) {
            int codeb = nt * 8 + (l >> 2);
            uint4 v0 = sB[codeb * 9 + q * 2];
            uint4 v1 = sB[codeb * 9 + q * 2 + 1];
            float2 sq = *(float2*)&sSq[nt * 8 + 2 * q];
            unsigned ce = (unsigned)(c0 + nt * 8 + 2 * q), co = ce + 1;
            #pragma unroll
            for (int t = 0; t < 2; t++) {
                // two independent depth-2 accumulation chains per m-tile
                float a0 = sq.x, a1 = sq.y, a2 = sq.x, a3 = sq.y;   // bias-seeded
                float b0 = 0.f, b1 = 0.f, b2 = 0.f, b3 = 0.f;
                mma_bf16(a0, a1, a2, a3, afr[t][0], v0.x, v0.y);
                mma_bf16(b0, b1, b2, b3, afr[t][2], v1.x, v1.y);
                mma_bf16(a0, a1, a2, a3, afr[t][1], v0.z, v0.w);
                mma_bf16(b0, b1, b2, b3, afr[t][3], v1.z, v1.w);
                float va = a0 + b0, vb = a1 + b1;   // row l/4 (+t*16), codes ce/co
                float vc = a2 + b2, vd = a3 + b3;   // row l/4+8 (+t*16)
                int m0 = 2 * t, m1 = 2 * t + 1;
                INS3(Kk[m0][0], Kk[m0][1], Kk[m0][2],
                     (__float_as_uint(va) & 0xFFFFFC00u) | ce);
                INS3(Kk[m0][0], Kk[m0][1], Kk[m0][2],
                     (__float_as_uint(vb) & 0xFFFFFC00u) | co);
                INS3(Kk[m1][0], Kk[m1][1], Kk[m1][2],
                     (__float_as_uint(vc) & 0xFFFFFC00u) | ce);
                INS3(Kk[m1][0], Kk[m1][1], Kk[m1][2],
                     (__float_as_uint(vd) & 0xFFFFFC00u) | co);
            }
        }
    }

    // writeout: 12 candidates per row (3 per quad lane), R9 row mapping
    #pragma unroll
    for (int m = 0; m < 4; m++) {
        int grow = rowbase + w * 32 + (m & 1) * 8 + (m >> 1) * 16 + (l >> 2);
        g_c12[grow * 4 + q] = make_uint4(Kk[m][0], Kk[m][1], Kk[m][2], 0xFFFFFFFFu);
    }
}

// ---------------- finish: rescue (top-4 exact / warp full scan / H1) + gather + loss ----
__global__ void __launch_bounds__(256) vq_finish(const float* __restrict__ x,
                                                 float* __restrict__ out) {
    __shared__ int    sIdx[256];
    __shared__ double sred[8];
    int tid = threadIdx.x, lane = tid & 31;
    int row = blockIdx.x * 256 + tid;

    unsigned K0 = 0xFFFFFFFFu, K1 = 0xFFFFFFFFu, K2 = 0xFFFFFFFFu, K3 = 0xFFFFFFFFu;
    #pragma unroll
    for (int j = 0; j < 4; j++) {
        uint4 c = g_c12[row * 4 + j];
        INS4(K0, K1, K2, K3, c.x);
        INS4(K0, K1, K2, K3, c.y);
        INS4(K0, K1, K2, K3, c.z);
    }
    float s0 = __uint_as_float(K0 & 0xFFFFFC00u);
    float s1 = __uint_as_float(K1 & 0xFFFFFC00u);
    float s3 = __uint_as_float(K3 & 0xFFFFFC00u);
    int widx = (int)(K0 & 1023u);
    bool rescue = (s1 - s0 < GAP_ACCEPT);
    bool full   = rescue && (s3 - s0 < CLUSTER);

    // warp-cooperative exact full scans for clustered rows (rare)
    unsigned fmask = __ballot_sync(0xffffffffu, full);
    while (fmask) {
        int src = __ffs(fmask) - 1;
        fmask &= fmask - 1;
        int r = __shfl_sync(0xffffffffu, row, src);
        const float* xg = x + (size_t)r * D;
        float b0 = 3e38f, b1 = 3e38f;
        int i0 = 0, i1 = 0;
        for (int k = lane; k < K; k += 32) {
            const float* e = &g_embT[k * D];
            float dot = 0.f;
            #pragma unroll 8
            for (int d = 0; d < D; d++) dot = fmaf(xg[d], e[d], dot);
            float val = fmaf(dot, -2.f, g_sqe[k]);
            if (val < b0)      { b1 = b0; i1 = i0; b0 = val; i0 = k; }
            else if (val < b1) { b1 = val; i1 = k; }
        }
        #pragma unroll
        for (int off = 16; off; off >>= 1) {
            float ob0 = __shfl_xor_sync(0xffffffffu, b0, off);
            float ob1 = __shfl_xor_sync(0xffffffffu, b1, off);
            int   oi0 = __shfl_xor_sync(0xffffffffu, i0, off);
            int   oi1 = __shfl_xor_sync(0xffffffffu, i1, off);
            bool owin = (ob0 < b0) || (ob0 == b0 && oi0 < i0);
            if (owin) {
                float tf = b0; b0 = ob0; ob0 = tf;
                int   ti = i0; i0 = oi0; oi0 = ti;
                tf = b1; b1 = ob1; ob1 = tf;
                ti = i1; i1 = oi1; oi1 = ti;
            }
            if ((ob0 < b1) || (ob0 == b1 && oi0 < i1)) { b1 = ob0; i1 = oi0; }
        }
        if (lane == src)
            widx = (b1 - b0 < 1e-3f) ? h1_emulate_g(xg, min(i0, i1), max(i0, i1)) : i0;
    }

    if (rescue && !full) {
        const float* xg = x + (size_t)row * D;
        int ids[4] = { (int)(K0 & 1023u), (int)(K1 & 1023u),
                       (int)(K2 & 1023u), (int)(K3 & 1023u) };
        #pragma unroll
        for (int a = 1; a < 4; a++) {
            int v = ids[a], b = a;
            while (b > 0 && ids[b - 1] > v) { ids[b] = ids[b - 1]; b--; }
            ids[b] = v;
        }
        float b0 = 3e38f, b1 = 3e38f;
        int i0 = 0, i1 = 0;
        #pragma unroll
        for (int j = 0; j < 4; j++) {
            const float* e = &g_embT[ids[j] * D];
            float dot = 0.f;
            #pragma unroll 8
            for (int d = 0; d < D; d++) dot = fmaf(xg[d], e[d], dot);
            float val = fmaf(dot, -2.f, g_sqe[ids[j]]);
            if (val < b0)      { b1 = b0; i1 = i0; b0 = val; i0 = ids[j]; }
            else if (val < b1) { b1 = val; i1 = ids[j]; }
        }
        widx = (b1 - b0 < 1e-3f) ? h1_emulate_g(xg, min(i0, i1), max(i0, i1)) : i0;
    }
    sIdx[tid] = widx;
    __syncthreads();

    // phase B: block's 256 rows -> straight-through output + double loss accum
    size_t base = (size_t)blockIdx.x * 256 * D;
    double local = 0.0;
    #pragma unroll
    for (int it = 0; it < 16; it++) {
        int j = it * 256 + tid;          // 0..4095 float4s
        int r = j >> 4, dd = j & 15;
        int idx = sIdx[r];
        float4 qv = ((const float4*)g_embT)[idx * 16 + dd];
        float4 xv = *(const float4*)(x + base + (size_t)j * 4);
        float d0 = qv.x - xv.x, d1 = qv.y - xv.y, d2 = qv.z - xv.z, d3 = qv.w - xv.w;
        float4 o;
        o.x = xv.x + d0; o.y = xv.y + d1; o.z = xv.z + d2; o.w = xv.w + d3;
        *(float4*)(out + base + (size_t)j * 4) = o;
        local += (double)d0 * d0 + (double)d1 * d1 + (double)d2 * d2 + (double)d3 * d3;
    }
    #pragma unroll
    for (int off = 16; off > 0; off >>= 1)
        local += __shfl_down_sync(0xffffffffu, local, off);
    int w = tid >> 5;
    if (lane == 0) sred[w] = local;
    __syncthreads();
    if (tid == 0) {
        double s = 0.0;
        #pragma unroll
        for (int k = 0; k < 8; k++) s += sred[k];
        atomicAdd(&g_acc, s);
    }
}

__global__ void vq_finalize_kernel(float* __restrict__ loss_out) {
    double m = g_acc / (double)((long)NROWS * D);
    float lf = (float)m;
    *loss_out = 0.25f * lf + lf;   // BETA*commitment + codebook (equal values)
}

extern "C" void kernel_launch(void* const* d_in, const int* in_sizes, int n_in,
                              void* d_out, int out_size) {
    const float* x   = (const float*)d_in[0];   // [256,32,32,64] fp32
    const float* emb = (const float*)d_in[1];   // [64,1024] fp32
    float* out = (float*)d_out;

    cudaFuncSetAttribute(vq_coarse, cudaFuncAttributeMaxDynamicSharedMemorySize, SMEM_SZ);

    vq_init_kernel<<<256, 256>>>(emb);
    vq_coarse<<<NROWS / TILE_M, 128, SMEM_SZ>>>(x);
    vq_finish<<<NROWS / 256, 256>>>(x, out);
    vq_finalize_kernel<<<1, 1>>>(out + (out_size - 1));
}